// round 5
// baseline (speedup 1.0000x reference)
#include <cuda_runtime.h>
#include <cuda_bf16.h>
#include <cstdint>

// ---------------- problem constants ----------------
// BS=256, C=256, H=W=16, HW=256
// feat channels: [0:256)=relu(f1), [256:512)=corr1, [512:768)=relu(f2), [768:1024)=corr2
// conv1: 1024->1024 3x3 SAME, conv2: 1024->512 3x3 SAME
// cls: 512 -> 512 (=2*256) 1x1, psroi-diag, avgpool(16x16), softmax(2)
// output: cls_prob(512) | corr1(16777216) | corr2(16777216), fp32

#define NB        256
#define HW        256
#define CH        256
#define OFF_C1    512
#define OFF_C2    (512 + 16777216)

// ---------------- device scratch (static: no allocs allowed) ----------------
__device__ __nv_bfloat16 g_XIN[(size_t)NB * 1024 * HW];   // conv1 input (concat), bf16
__device__ __nv_bfloat16 g_Y1 [(size_t)NB * 1024 * HW];   // conv1 output
__device__ __nv_bfloat16 g_Y2 [(size_t)NB *  512 * HW];   // conv2 output
__device__ float         g_invn1[NB * HW];
__device__ float         g_invn2[NB * HW];
__device__ __nv_bfloat16 g_W1[(size_t)8 * 64 * 9 * 128 * 16]; // conv1 w, swizzled bf16
__device__ __nv_bfloat16 g_W2[(size_t)4 * 64 * 9 * 128 * 16]; // conv2 w
__device__ float         g_wclsT[512 * 512];                  // cls w, transposed [ic][o]

// ---------------- K0: relu + channel-norms + bf16 copies ----------------
__global__ void k_norm(const float* __restrict__ f1, const float* __restrict__ f2,
                       __nv_bfloat16* __restrict__ xin,
                       float* __restrict__ invn1, float* __restrict__ invn2) {
    int b = blockIdx.x, p = threadIdx.x;
    const float* f1b = f1 + (size_t)b * 65536;
    const float* f2b = f2 + (size_t)b * 65536;
    __nv_bfloat16* xb = xin + (size_t)b * 262144;
    float s1 = 0.f, s2 = 0.f;
    #pragma unroll 4
    for (int c = 0; c < CH; ++c) {
        float v1 = fmaxf(f1b[c * HW + p], 0.f);
        float v2 = fmaxf(f2b[c * HW + p], 0.f);
        s1 += v1 * v1;  s2 += v2 * v2;
        xb[c * HW + p]         = __float2bfloat16(v1);
        xb[(512 + c) * HW + p] = __float2bfloat16(v2);
    }
    invn1[b * HW + p] = 1.0f / fmaxf(sqrtf(s1), 1e-12f);
    invn2[b * HW + p] = 1.0f / fmaxf(sqrtf(s2), 1e-12f);
}

// ---------------- weight prep ----------------
// out[(((ocb*64+cc)*9+tp)*128+oo)*16+ii] = w[(ocb*128+oo)*9216 + (cc*16+ii)*9 + tp]
__global__ void k_prepw(const float* __restrict__ w, __nv_bfloat16* __restrict__ o, int total) {
    int idx = blockIdx.x * blockDim.x + threadIdx.x;
    if (idx >= total) return;
    int ii = idx & 15;  int r = idx >> 4;
    int oo = r & 127;   r >>= 7;
    int tp = r % 9;     r /= 9;
    int cc = r & 63;    int ocb = r >> 6;
    int oc = ocb * 128 + oo;
    int ic = cc * 16 + ii;
    o[idx] = __float2bfloat16(w[(size_t)oc * 9216 + (size_t)ic * 9 + tp]);
}

__global__ void k_prepcls(const float* __restrict__ w, float* __restrict__ o) {
    int idx = blockIdx.x * blockDim.x + threadIdx.x;  // idx = ic*512 + oc
    if (idx >= 512 * 512) return;
    int ic = idx >> 9, oc = idx & 511;
    o[idx] = w[oc * 512 + ic];
}

// ---------------- K1: correlation GEMM (fp32), writes corr1+corr2 + bf16 copies ----------------
// corr1[b][k][p] = (sum_c relu(f2)[c][k] * relu(f1)[c][p]) * invn2[k] * invn1[p]
__global__ void __launch_bounds__(256) k_corr(
        const float* __restrict__ f1, const float* __restrict__ f2,
        float* __restrict__ out,
        const float* __restrict__ invn1, const float* __restrict__ invn2,
        __nv_bfloat16* __restrict__ xin) {
    __shared__ float A_s[16][132];
    __shared__ float B_s[16][132];
    int b = blockIdx.x, q = blockIdx.y;
    int kb = (q >> 1) * 128, pb = (q & 1) * 128;
    int t = threadIdx.x, tx = t & 15, ty = t >> 4;
    const float* f1b = f1 + (size_t)b * 65536;
    const float* f2b = f2 + (size_t)b * 65536;

    float acc[8][8];
    #pragma unroll
    for (int i = 0; i < 8; ++i)
        #pragma unroll
        for (int j = 0; j < 8; ++j) acc[i][j] = 0.f;

    for (int cc = 0; cc < 16; ++cc) {
        #pragma unroll
        for (int u = 0; u < 8; ++u) {
            int e = t + 256 * u;
            int c = e >> 7, k = e & 127;
            A_s[c][k] = fmaxf(f2b[(cc * 16 + c) * HW + kb + k], 0.f);
            B_s[c][k] = fmaxf(f1b[(cc * 16 + c) * HW + pb + k], 0.f);
        }
        __syncthreads();
        #pragma unroll
        for (int c = 0; c < 16; ++c) {
            float4 a0 = *(const float4*)&A_s[c][ty * 8];
            float4 a1 = *(const float4*)&A_s[c][ty * 8 + 4];
            float4 b0 = *(const float4*)&B_s[c][tx * 8];
            float4 b1 = *(const float4*)&B_s[c][tx * 8 + 4];
            float av[8] = {a0.x, a0.y, a0.z, a0.w, a1.x, a1.y, a1.z, a1.w};
            float bv[8] = {b0.x, b0.y, b0.z, b0.w, b1.x, b1.y, b1.z, b1.w};
            #pragma unroll
            for (int i = 0; i < 8; ++i)
                #pragma unroll
                for (int j = 0; j < 8; ++j) acc[i][j] += av[i] * bv[j];
        }
        __syncthreads();
    }

    float ik[8], ip[8];
    #pragma unroll
    for (int i = 0; i < 8; ++i) ik[i] = invn2[b * HW + kb + ty * 8 + i];
    #pragma unroll
    for (int j = 0; j < 8; ++j) ip[j] = invn1[b * HW + pb + tx * 8 + j];

    float* c1 = out + OFF_C1 + (size_t)b * 65536;
    float* c2 = out + OFF_C2 + (size_t)b * 65536;
    __nv_bfloat16* xb = xin + (size_t)b * 262144;

    #pragma unroll
    for (int i = 0; i < 8; ++i) {
        int k = kb + ty * 8 + i;
        #pragma unroll
        for (int j = 0; j < 8; ++j) {
            int p = pb + tx * 8 + j;
            float v = acc[i][j] * ik[i] * ip[j];
            c1[k * HW + p] = v;
            c2[p * HW + k] = v;
            __nv_bfloat16 vb = __float2bfloat16(v);
            xb[(256 + k) * HW + p] = vb;   // corr1 channels
            xb[(768 + p) * HW + k] = vb;   // corr2 channels (transposed)
        }
    }
}

// ---------------- conv 3x3 implicit GEMM (bf16 mma.sync, fp32 accum) ----------------
__device__ __forceinline__ void mma16816(float* c, const uint32_t* a, uint32_t b0, uint32_t b1) {
    asm volatile(
        "mma.sync.aligned.m16n8k16.row.col.f32.bf16.bf16.f32 "
        "{%0,%1,%2,%3}, {%4,%5,%6,%7}, {%8,%9}, {%0,%1,%2,%3};\n"
        : "+f"(c[0]), "+f"(c[1]), "+f"(c[2]), "+f"(c[3])
        : "r"(a[0]), "r"(a[1]), "r"(a[2]), "r"(a[3]), "r"(b0), "r"(b1));
}

// grid = (256 batches, OC/128). block = 512 threads (16 warps, 4M x 4N).
// block tile: M=128 oc, N=256 pixels (full image), K = 1024 ic x 9 taps.
__global__ void __launch_bounds__(512, 1) k_conv(
        const __nv_bfloat16* __restrict__ Xin,   // [b][1024][256]
        const __nv_bfloat16* __restrict__ Wg,    // [ocb][cc][tap][128][16]
        const float* __restrict__ bias,
        __nv_bfloat16* __restrict__ Yout,        // [b][OC][256]
        int OC) {
    __shared__ __align__(16) __nv_bfloat16 X_s[256][18];       // [pixel][ic16] (+pad)
    __shared__ __align__(16) __nv_bfloat16 W_s[9][128][16];    // [tap][oc][ic16]

    int b = blockIdx.x, ocb = blockIdx.y;
    int t = threadIdx.x;
    int lane = t & 31, wid = t >> 5;
    int g = lane >> 2, tg = lane & 3;
    int wm = (wid & 3) * 32;    // warp oc base within block
    int wn = (wid >> 2) * 64;   // warp pixel base

    const __nv_bfloat16* xb = Xin + (size_t)b * 262144;
    const __nv_bfloat16* wb = Wg + (size_t)ocb * (64 * 9 * 2048);

    float acc[2][8][4];
    #pragma unroll
    for (int mi = 0; mi < 2; ++mi)
        #pragma unroll
        for (int j = 0; j < 8; ++j)
            #pragma unroll
            for (int r = 0; r < 4; ++r) acc[mi][j][r] = 0.f;

    int yj[8], xjj[8];
    #pragma unroll
    for (int j = 0; j < 8; ++j) {
        int p = wn + j * 8 + g;
        yj[j] = p >> 4; xjj[j] = p & 15;
    }

    for (int cc = 0; cc < 64; ++cc) {
        // stage input chunk [16 ic][256 px] -> X_s[px][ic]
        #pragma unroll
        for (int u = 0; u < 8; ++u) {
            int e = t + 512 * u;
            int i = e >> 8, p = e & 255;
            X_s[p][i] = xb[(cc * 16 + i) * HW + p];
        }
        // stage weights [9][128][16] (contiguous in global)
        {
            const uint2* wsrc = (const uint2*)(wb + (size_t)cc * (9 * 2048));
            uint2* wdst = (uint2*)(&W_s[0][0][0]);
            #pragma unroll
            for (int u = 0; u < 9; ++u) {
                int v = t + 512 * u;
                if (v < 4608) wdst[v] = wsrc[v];
            }
        }
        __syncthreads();

        #pragma unroll
        for (int tap = 0; tap < 9; ++tap) {
            const int dy = tap / 3 - 1, dx = tap % 3 - 1;
            uint32_t a[2][4];
            #pragma unroll
            for (int mi = 0; mi < 2; ++mi) {
                const __nv_bfloat16* wr = &W_s[tap][wm + mi * 16 + g][0];
                a[mi][0] = *(const uint32_t*)(wr + 2 * tg);
                a[mi][1] = *(const uint32_t*)(wr + 128 + 2 * tg);       // +8 rows * 16
                a[mi][2] = *(const uint32_t*)(wr + 2 * tg + 8);
                a[mi][3] = *(const uint32_t*)(wr + 128 + 2 * tg + 8);
            }
            #pragma unroll
            for (int j = 0; j < 8; ++j) {
                int yy = yj[j] + dy, xx = xjj[j] + dx;
                uint32_t b0 = 0u, b1 = 0u;
                if ((unsigned)yy < 16u && (unsigned)xx < 16u) {
                    const __nv_bfloat16* xr = &X_s[yy * 16 + xx][0];
                    b0 = *(const uint32_t*)(xr + 2 * tg);
                    b1 = *(const uint32_t*)(xr + 2 * tg + 8);
                }
                mma16816(acc[0][j], a[0], b0, b1);
                mma16816(acc[1][j], a[1], b0, b1);
            }
        }
        __syncthreads();
    }

    // epilogue: +bias, relu, bf16 store
    __nv_bfloat16* yb = Yout + (size_t)b * OC * HW;
    #pragma unroll
    for (int mi = 0; mi < 2; ++mi) {
        int oc0 = ocb * 128 + wm + mi * 16 + g;
        int oc1 = oc0 + 8;
        float bz0 = bias[oc0], bz1 = bias[oc1];
        #pragma unroll
        for (int j = 0; j < 8; ++j) {
            int p0 = wn + j * 8 + 2 * tg;
            const float* ac = acc[mi][j];
            __nv_bfloat162 v0, v1;
            v0.x = __float2bfloat16(fmaxf(ac[0] + bz0, 0.f));
            v0.y = __float2bfloat16(fmaxf(ac[1] + bz0, 0.f));
            v1.x = __float2bfloat16(fmaxf(ac[2] + bz1, 0.f));
            v1.y = __float2bfloat16(fmaxf(ac[3] + bz1, 0.f));
            *(__nv_bfloat162*)(&yb[(size_t)oc0 * HW + p0]) = v0;
            *(__nv_bfloat162*)(&yb[(size_t)oc1 * HW + p0]) = v1;
        }
    }
}

// ---------------- final head: 1x1 conv (diag only) + avgpool + softmax ----------------
__global__ void k_final(const __nv_bfloat16* __restrict__ Y2,
                        const float* __restrict__ wT,     // [ic][o], o = c*256+p
                        float* __restrict__ out) {
    int b = blockIdx.x, p = threadIdx.x;
    const __nv_bfloat16* yb = Y2 + (size_t)b * 131072;
    float a0 = 0.f, a1 = 0.f;
    #pragma unroll 8
    for (int ic = 0; ic < 512; ++ic) {
        float y = __bfloat162float(yb[ic * HW + p]);
        a0 += wT[ic * 512 + p] * y;
        a1 += wT[ic * 512 + 256 + p] * y;
    }
    a0 = fmaxf(a0, 0.f);
    a1 = fmaxf(a1, 0.f);
    __shared__ float s0[256], s1[256];
    s0[p] = a0; s1[p] = a1;
    __syncthreads();
    for (int st = 128; st > 0; st >>= 1) {
        if (p < st) { s0[p] += s0[p + st]; s1[p] += s1[p + st]; }
        __syncthreads();
    }
    if (p == 0) {
        float m0 = s0[0] * (1.0f / 256.0f);
        float m1 = s1[0] * (1.0f / 256.0f);
        float mx = fmaxf(m0, m1);
        float e0 = expf(m0 - mx), e1 = expf(m1 - mx);
        float inv = 1.0f / (e0 + e1);
        out[b * 2 + 0] = e0 * inv;
        out[b * 2 + 1] = e1 * inv;
    }
}

// ---------------- launch ----------------
extern "C" void kernel_launch(void* const* d_in, const int* in_sizes, int n_in,
                              void* d_out, int out_size) {
    const float* f1      = (const float*)d_in[0];
    const float* f2      = (const float*)d_in[1];
    const float* conv1_w = (const float*)d_in[2];
    const float* conv1_b = (const float*)d_in[3];
    const float* conv2_w = (const float*)d_in[4];
    const float* conv2_b = (const float*)d_in[5];
    const float* cls_w   = (const float*)d_in[6];
    float* out = (float*)d_out;

    __nv_bfloat16 *xin, *y1, *y2, *w1, *w2;
    float *invn1, *invn2, *wclsT;
    cudaGetSymbolAddress((void**)&xin,   g_XIN);
    cudaGetSymbolAddress((void**)&y1,    g_Y1);
    cudaGetSymbolAddress((void**)&y2,    g_Y2);
    cudaGetSymbolAddress((void**)&w1,    g_W1);
    cudaGetSymbolAddress((void**)&w2,    g_W2);
    cudaGetSymbolAddress((void**)&invn1, g_invn1);
    cudaGetSymbolAddress((void**)&invn2, g_invn2);
    cudaGetSymbolAddress((void**)&wclsT, g_wclsT);

    // prep
    k_norm<<<NB, 256>>>(f1, f2, xin, invn1, invn2);
    {
        int tot1 = 8 * 64 * 9 * 2048;  // 9,437,184
        k_prepw<<<(tot1 + 255) / 256, 256>>>(conv1_w, w1, tot1);
        int tot2 = 4 * 64 * 9 * 2048;  // 4,718,592
        k_prepw<<<(tot2 + 255) / 256, 256>>>(conv2_w, w2, tot2);
        k_prepcls<<<(512 * 512 + 255) / 256, 256>>>(cls_w, wclsT);
    }
    // correlation (writes corr1 + corr2 to d_out, bf16 copies into xin)
    k_corr<<<dim3(NB, 4), 256>>>(f1, f2, out, invn1, invn2, xin);
    // convs
    k_conv<<<dim3(NB, 8), 512>>>(xin, w1, conv1_b, y1, 1024);
    k_conv<<<dim3(NB, 4), 512>>>(y1,  w2, conv2_b, y2, 512);
    // head
    k_final<<<NB, 256>>>(y2, wclsT, out);
}

// round 8
// speedup vs baseline: 1.2860x; 1.2860x over previous
#include <cuda_runtime.h>
#include <cuda_bf16.h>
#include <cstdint>

#define NB 256
#define HW 256
#define CH 256
#define OFF_C1 512
#define OFF_C2 (512 + 16777216)

// conv smem layout: X rows padded to 48B (16 ic used), zero row at 256
#define XBYTES (257 * 48)            // 12336
#define XOFF0  0
#define XOFF1  12336
#define WOFF0  24672
#define WBYTES (9 * 128 * 48)        // 55296
#define WOFF1  (24672 + 55296)       // 79968
#define SMEMC  (79968 + 55296)       // 135264

// ---------------- device scratch ----------------
__device__ __nv_bfloat16 g_XIN[(size_t)NB * 1024 * HW];   // [img][64 chunk][256 px][16 ic]
__device__ __nv_bfloat16 g_Y1 [(size_t)NB * 1024 * HW];   // same layout, conv1 out
__device__ __nv_bfloat16 g_Y2 [(size_t)NB *  512 * HW];   // [img][32 chunk][256][16]
__device__ float         g_invn1[NB * HW];
__device__ float         g_invn2[NB * HW];
__device__ __nv_bfloat16 g_W1[(size_t)8 * 64 * 9 * 128 * 16];  // [ocb][cc][tap][128][16]
__device__ __nv_bfloat16 g_W2[(size_t)4 * 64 * 9 * 128 * 16];
__device__ float         g_wclsT[512 * 512];

// ---------------- PTX helpers (sm_80-era only: safe on compute_103) ----------------
__device__ __forceinline__ uint32_t smem_u32(const void* p) {
    uint32_t a;
    asm("{ .reg .u64 t; cvta.to.shared.u64 t, %1; cvt.u32.u64 %0, t; }" : "=r"(a) : "l"(p));
    return a;
}
#define CP16(dst, src) \
    asm volatile("cp.async.ca.shared.global [%0], [%1], 16;" :: "r"(dst), "l"(src))
#define CPCOMMIT() asm volatile("cp.async.commit_group;")
#define CPWAIT0()  asm volatile("cp.async.wait_group 0;")
#define LDSM4(r0, r1, r2, r3, a) \
    asm volatile("ldmatrix.sync.aligned.m8n8.x4.shared.b16 {%0,%1,%2,%3}, [%4];" \
        : "=r"(r0), "=r"(r1), "=r"(r2), "=r"(r3) : "r"(a))
__device__ __forceinline__ void mma16816(float* c, const uint32_t* a, uint32_t b0, uint32_t b1) {
    asm volatile(
        "mma.sync.aligned.m16n8k16.row.col.f32.bf16.bf16.f32 "
        "{%0,%1,%2,%3}, {%4,%5,%6,%7}, {%8,%9}, {%0,%1,%2,%3};\n"
        : "+f"(c[0]), "+f"(c[1]), "+f"(c[2]), "+f"(c[3])
        : "r"(a[0]), "r"(a[1]), "r"(a[2]), "r"(a[3]), "r"(b0), "r"(b1));
}

// ---------------- K0: relu + channel norms + chunked bf16 layout ----------------
__global__ void k_norm(const float* __restrict__ f1, const float* __restrict__ f2,
                       __nv_bfloat16* __restrict__ xin,
                       float* __restrict__ invn1, float* __restrict__ invn2) {
    int b = blockIdx.x, p = threadIdx.x;
    const float* f1b = f1 + (size_t)b * 65536;
    const float* f2b = f2 + (size_t)b * 65536;
    __nv_bfloat16* xb = xin + (size_t)b * 262144;
    float s1 = 0.f, s2 = 0.f;
    for (int ch = 0; ch < 16; ++ch) {
        __nv_bfloat16 h1[16], h2[16];
        #pragma unroll
        for (int i = 0; i < 16; ++i) {
            float v1 = fmaxf(f1b[(ch * 16 + i) * HW + p], 0.f);
            float v2 = fmaxf(f2b[(ch * 16 + i) * HW + p], 0.f);
            s1 += v1 * v1;  s2 += v2 * v2;
            h1[i] = __float2bfloat16(v1);
            h2[i] = __float2bfloat16(v2);
        }
        *(uint4*)&xb[(size_t)ch * 4096 + p * 16]            = *(uint4*)&h1[0];
        *(uint4*)&xb[(size_t)ch * 4096 + p * 16 + 8]        = *(uint4*)&h1[8];
        *(uint4*)&xb[(size_t)(32 + ch) * 4096 + p * 16]     = *(uint4*)&h2[0];
        *(uint4*)&xb[(size_t)(32 + ch) * 4096 + p * 16 + 8] = *(uint4*)&h2[8];
    }
    invn1[b * HW + p] = 1.0f / fmaxf(sqrtf(s1), 1e-12f);
    invn2[b * HW + p] = 1.0f / fmaxf(sqrtf(s2), 1e-12f);
}

// ---------------- weight prep: [ocb][cc][tap][128 oc][16 ic] ----------------
__global__ void k_prepw(const float* __restrict__ w, __nv_bfloat16* __restrict__ o,
                        int IC, int NCC, int total) {
    int idx = blockIdx.x * blockDim.x + threadIdx.x;
    if (idx >= total) return;
    int ii = idx & 15;
    int oo = (idx >> 4) & 127;
    int r  = idx >> 11;
    int tp = r % 9;  r /= 9;
    int cc = r % NCC; int ocb = r / NCC;
    int oc = ocb * 128 + oo;
    int ic = cc * 16 + ii;
    o[idx] = __float2bfloat16(w[((size_t)oc * IC + ic) * 9 + tp]);
}

__global__ void k_prepcls(const float* __restrict__ w, float* __restrict__ o) {
    int idx = blockIdx.x * blockDim.x + threadIdx.x;
    if (idx >= 512 * 512) return;
    int ic = idx >> 9, oc = idx & 511;
    o[idx] = w[oc * 512 + ic];
}

// ---------------- K1: correlation GEMM (fp32 outputs + chunked bf16 copies) ----------------
__global__ void __launch_bounds__(256) k_corr(
        const float* __restrict__ f1, const float* __restrict__ f2,
        float* __restrict__ out,
        const float* __restrict__ invn1, const float* __restrict__ invn2,
        __nv_bfloat16* __restrict__ xin) {
    __shared__ float A_s[16][132];
    __shared__ float B_s[16][132];
    int b = blockIdx.x, q = blockIdx.y;
    int kb = (q >> 1) * 128, pb = (q & 1) * 128;
    int t = threadIdx.x, tx = t & 15, ty = t >> 4;
    const float* f1b = f1 + (size_t)b * 65536;
    const float* f2b = f2 + (size_t)b * 65536;
    float acc[8][8];
    #pragma unroll
    for (int i = 0; i < 8; ++i)
        #pragma unroll
        for (int j = 0; j < 8; ++j) acc[i][j] = 0.f;
    for (int cc = 0; cc < 16; ++cc) {
        #pragma unroll
        for (int u = 0; u < 8; ++u) {
            int e = t + 256 * u;
            int c = e >> 7, k = e & 127;
            A_s[c][k] = fmaxf(f2b[(cc * 16 + c) * HW + kb + k], 0.f);
            B_s[c][k] = fmaxf(f1b[(cc * 16 + c) * HW + pb + k], 0.f);
        }
        __syncthreads();
        #pragma unroll
        for (int c = 0; c < 16; ++c) {
            float4 a0 = *(const float4*)&A_s[c][ty * 8];
            float4 a1 = *(const float4*)&A_s[c][ty * 8 + 4];
            float4 b0 = *(const float4*)&B_s[c][tx * 8];
            float4 b1 = *(const float4*)&B_s[c][tx * 8 + 4];
            float av[8] = {a0.x, a0.y, a0.z, a0.w, a1.x, a1.y, a1.z, a1.w};
            float bv[8] = {b0.x, b0.y, b0.z, b0.w, b1.x, b1.y, b1.z, b1.w};
            #pragma unroll
            for (int i = 0; i < 8; ++i)
                #pragma unroll
                for (int j = 0; j < 8; ++j) acc[i][j] += av[i] * bv[j];
        }
        __syncthreads();
    }
    float ik[8], ip[8];
    #pragma unroll
    for (int i = 0; i < 8; ++i) ik[i] = invn2[b * HW + kb + ty * 8 + i];
    #pragma unroll
    for (int j = 0; j < 8; ++j) ip[j] = invn1[b * HW + pb + tx * 8 + j];

    float vm[8][8];
    #pragma unroll
    for (int i = 0; i < 8; ++i)
        #pragma unroll
        for (int j = 0; j < 8; ++j) vm[i][j] = acc[i][j] * ik[i] * ip[j];

    float* c1 = out + OFF_C1 + (size_t)b * 65536;
    float* c2 = out + OFF_C2 + (size_t)b * 65536;
    #pragma unroll
    for (int i = 0; i < 8; ++i) {
        int k = kb + ty * 8 + i;
        #pragma unroll
        for (int j = 0; j < 8; ++j) {
            int p = pb + tx * 8 + j;
            c1[k * HW + p] = vm[i][j];
            c2[p * HW + k] = vm[i][j];
        }
    }
    // bf16 copies into chunked layout: corr1 -> chunks 16..31, corr2 -> 48..63
    __nv_bfloat16* xb = xin + (size_t)b * 262144;
    int ch1 = 16 + (kb >> 4) + (ty >> 1);
    int sl1 = (ty & 1) * 8;
    #pragma unroll
    for (int j = 0; j < 8; ++j) {
        int p = pb + tx * 8 + j;
        __nv_bfloat16 h[8];
        #pragma unroll
        for (int i = 0; i < 8; ++i) h[i] = __float2bfloat16(vm[i][j]);
        *(uint4*)&xb[(size_t)ch1 * 4096 + p * 16 + sl1] = *(uint4*)&h[0];
    }
    int ch2 = 48 + (pb >> 4) + (tx >> 1);
    int sl2 = (tx & 1) * 8;
    #pragma unroll
    for (int i = 0; i < 8; ++i) {
        int k = kb + ty * 8 + i;
        __nv_bfloat16 h[8];
        #pragma unroll
        for (int j = 0; j < 8; ++j) h[j] = __float2bfloat16(vm[i][j]);
        *(uint4*)&xb[(size_t)ch2 * 4096 + k * 16 + sl2] = *(uint4*)&h[0];
    }
}

// ---------------- conv 3x3 implicit GEMM: ldmatrix + cp.async double-buffer ----------------
// grid (OC/128, NB), 512 threads = 16 warps (4M x 4N). Block tile M=128 oc, N=256 px.
__global__ void __launch_bounds__(512, 1) k_conv(
        const __nv_bfloat16* __restrict__ Xin,  // [img][NCC][256][16]
        const __nv_bfloat16* __restrict__ Wg,   // [ocb][NCC][9][128][16]
        const float* __restrict__ bias,
        __nv_bfloat16* __restrict__ Y,          // [img][OC/16][256][16]
        int OC, int NCC) {
    extern __shared__ __align__(16) char sraw[];
    uint32_t sb = smem_u32(sraw);
    int img = blockIdx.y, ocb = blockIdx.x;
    int t = threadIdx.x, lane = t & 31, wid = t >> 5;
    int g = lane >> 2, tg = lane & 3;
    int wm = (wid & 3) * 32, wn = (wid >> 2) * 64;

    const char* xg = (const char*)(Xin + (size_t)img * NCC * 4096);
    const char* wg = (const char*)(Wg + (size_t)ocb * NCC * 18432);

    // zero rows (row 256 of both X buffers)
    if (t < 24) {
        int bi = t / 12, w = t % 12;
        *(uint32_t*)(sraw + (bi ? XOFF1 : XOFF0) + 12288 + w * 4) = 0u;
    }

    // per-lane ldmatrix address prep
    int r8 = lane & 7;
    uint32_t q1 = (lane >> 3) & 1;        // k-half (col +16B)
    int      q2 = (lane >> 4) & 1;        // j vs j+1
    uint32_t arel = (uint32_t)(wm + r8 + ((lane & 8) ? 8 : 0)) * 48 + ((lane & 16) ? 16 : 0);
    uint32_t xrel[4], mv[4];
    #pragma unroll
    for (int jj = 0; jj < 4; ++jj) {
        int px = wn + (2 * jj + q2) * 8 + r8;
        xrel[jj] = (uint32_t)px * 48 + q1 * 16;
        int xx = px & 15, yy = px >> 4;
        uint32_t m = 0;
        #pragma unroll
        for (int tp = 0; tp < 9; ++tp) {
            int dy = tp / 3 - 1, dx = tp % 3 - 1;
            if ((unsigned)(xx + dx) < 16u && (unsigned)(yy + dy) < 16u) m |= 1u << tp;
        }
        mv[jj] = m;
    }

    float acc[2][8][4];
    #pragma unroll
    for (int mi = 0; mi < 2; ++mi)
        #pragma unroll
        for (int j = 0; j < 8; ++j)
            #pragma unroll
            for (int r = 0; r < 4; ++r) acc[mi][j][r] = 0.f;

    // staging: X chunk 8KB (512x16B), W chunk 36KB (2304x16B), rows restrided to 48B
    auto stage = [&](int cc, int s) {
        uint32_t Xd = sb + (s ? XOFF1 : XOFF0);
        uint32_t Wd = sb + (s ? WOFF1 : WOFF0);
        const char* xs = xg + (size_t)cc * 8192;
        const char* ws = wg + (size_t)cc * 36864;
        { uint32_t d = Xd + (t >> 1) * 48 + (t & 1) * 16; CP16(d, xs + t * 16); }
        #pragma unroll
        for (int k2 = 0; k2 < 4; ++k2) {
            int ch = t + 512 * k2;
            uint32_t d = Wd + (ch >> 1) * 48 + (ch & 1) * 16;
            CP16(d, ws + (size_t)ch * 16);
        }
        if (t < 256) {
            int ch = 2048 + t;
            uint32_t d = Wd + (ch >> 1) * 48 + (ch & 1) * 16;
            CP16(d, ws + (size_t)ch * 16);
        }
    };

    stage(0, 0);
    CPCOMMIT();

    for (int cc = 0; cc < NCC; ++cc) {
        CPWAIT0();
        __syncthreads();
        if (cc + 1 < NCC) { stage(cc + 1, (cc + 1) & 1); CPCOMMIT(); }

        uint32_t Xa = sb + ((cc & 1) ? XOFF1 : XOFF0);
        uint32_t Wa = sb + ((cc & 1) ? WOFF1 : WOFF0);
        uint32_t za = Xa + 12288 + q1 * 16;
        uint32_t bb0 = Xa + xrel[0], bb1 = Xa + xrel[1];
        uint32_t bb2 = Xa + xrel[2], bb3 = Xa + xrel[3];
        uint32_t aA = Wa + arel;

        #pragma unroll
        for (int tp = 0; tp < 9; ++tp) {
            const int dy = tp / 3 - 1, dx = tp % 3 - 1;
            const int off = (dy * 16 + dx) * 48;
            uint32_t a0[4], a1[4];
            LDSM4(a0[0], a0[1], a0[2], a0[3], aA + tp * 6144);
            LDSM4(a1[0], a1[1], a1[2], a1[3], aA + tp * 6144 + 768);
            uint32_t bbv[4] = {bb0, bb1, bb2, bb3};
            #pragma unroll
            for (int jj = 0; jj < 4; ++jj) {
                uint32_t ba = ((mv[jj] >> tp) & 1u) ? (uint32_t)(bbv[jj] + off) : za;
                uint32_t b0, b1, b2, b3;
                LDSM4(b0, b1, b2, b3, ba);
                mma16816(acc[0][2 * jj],     a0, b0, b1);
                mma16816(acc[1][2 * jj],     a1, b0, b1);
                mma16816(acc[0][2 * jj + 1], a0, b2, b3);
                mma16816(acc[1][2 * jj + 1], a1, b2, b3);
            }
        }
    }

    // epilogue: bias + relu, transpose through smem, coalesced 16B stores
    __syncthreads();
    __nv_bfloat16* Sh = (__nv_bfloat16*)sraw;   // [256 px][136] (272B rows)
    #pragma unroll
    for (int mi = 0; mi < 2; ++mi) {
        int ocl = wm + mi * 16 + g;
        float bz0 = bias[ocb * 128 + ocl];
        float bz1 = bias[ocb * 128 + ocl + 8];
        #pragma unroll
        for (int j = 0; j < 8; ++j) {
            int px = wn + j * 8 + 2 * tg;
            const float* ac = acc[mi][j];
            Sh[px * 136 + ocl]           = __float2bfloat16(fmaxf(ac[0] + bz0, 0.f));
            Sh[(px + 1) * 136 + ocl]     = __float2bfloat16(fmaxf(ac[1] + bz0, 0.f));
            Sh[px * 136 + ocl + 8]       = __float2bfloat16(fmaxf(ac[2] + bz1, 0.f));
            Sh[(px + 1) * 136 + ocl + 8] = __float2bfloat16(fmaxf(ac[3] + bz1, 0.f));
        }
    }
    __syncthreads();
    uint4* Yg = (uint4*)(Y + ((size_t)img * (OC >> 4) + ocb * 8) * 4096);
    #pragma unroll
    for (int k2 = 0; k2 < 8; ++k2) {
        int idx = t + 512 * k2;               // 4096 = 8 chunks * 256 px * 2 halves
        int c8 = idx >> 9, rem = idx & 511, px = rem >> 1, hf = rem & 1;
        uint4 v = *(uint4*)&Sh[px * 136 + c8 * 16 + hf * 8];
        Yg[(c8 * 256 + px) * 2 + hf] = v;
    }
}

// ---------------- final head: 1x1 (diag) + avgpool + softmax ----------------
__global__ void k_final(const __nv_bfloat16* __restrict__ Y2,
                        const float* __restrict__ wT,
                        float* __restrict__ out) {
    int b = blockIdx.x, p = threadIdx.x;
    const uint4* yb = (const uint4*)(Y2 + (size_t)b * 131072);
    float a0 = 0.f, a1 = 0.f;
    for (int c = 0; c < 32; ++c) {
        uint4 u0 = yb[(c * 256 + p) * 2];
        uint4 u1 = yb[(c * 256 + p) * 2 + 1];
        __nv_bfloat16 h[16];
        *(uint4*)&h[0] = u0;
        *(uint4*)&h[8] = u1;
        const float* wr = wT + (size_t)c * 16 * 512 + p;
        #pragma unroll
        for (int i = 0; i < 16; ++i) {
            float y = __bfloat162float(h[i]);
            a0 += wr[i * 512] * y;
            a1 += wr[i * 512 + 256] * y;
        }
    }
    a0 = fmaxf(a0, 0.f);
    a1 = fmaxf(a1, 0.f);
    __shared__ float s0[256], s1[256];
    s0[p] = a0; s1[p] = a1;
    __syncthreads();
    for (int st = 128; st > 0; st >>= 1) {
        if (p < st) { s0[p] += s0[p + st]; s1[p] += s1[p + st]; }
        __syncthreads();
    }
    if (p == 0) {
        float m0 = s0[0] * (1.0f / 256.0f);
        float m1 = s1[0] * (1.0f / 256.0f);
        float mx = fmaxf(m0, m1);
        float e0 = expf(m0 - mx), e1 = expf(m1 - mx);
        float inv = 1.0f / (e0 + e1);
        out[b * 2 + 0] = e0 * inv;
        out[b * 2 + 1] = e1 * inv;
    }
}

// ---------------- launch ----------------
extern "C" void kernel_launch(void* const* d_in, const int* in_sizes, int n_in,
                              void* d_out, int out_size) {
    const float* f1      = (const float*)d_in[0];
    const float* f2      = (const float*)d_in[1];
    const float* conv1_w = (const float*)d_in[2];
    const float* conv1_b = (const float*)d_in[3];
    const float* conv2_w = (const float*)d_in[4];
    const float* conv2_b = (const float*)d_in[5];
    const float* cls_w   = (const float*)d_in[6];
    float* out = (float*)d_out;

    __nv_bfloat16 *xin, *y1, *y2, *w1, *w2;
    float *invn1, *invn2, *wclsT;
    cudaGetSymbolAddress((void**)&xin,   g_XIN);
    cudaGetSymbolAddress((void**)&y1,    g_Y1);
    cudaGetSymbolAddress((void**)&y2,    g_Y2);
    cudaGetSymbolAddress((void**)&w1,    g_W1);
    cudaGetSymbolAddress((void**)&w2,    g_W2);
    cudaGetSymbolAddress((void**)&invn1, g_invn1);
    cudaGetSymbolAddress((void**)&invn2, g_invn2);
    cudaGetSymbolAddress((void**)&wclsT, g_wclsT);

    cudaFuncSetAttribute(k_conv, cudaFuncAttributeMaxDynamicSharedMemorySize, SMEMC);

    k_norm<<<NB, 256>>>(f1, f2, xin, invn1, invn2);
    {
        int tot1 = 8 * 64 * 9 * 2048;   // 9,437,184
        k_prepw<<<(tot1 + 255) / 256, 256>>>(conv1_w, w1, 1024, 64, tot1);
        int tot2 = 4 * 64 * 9 * 2048;   // 4,718,592
        k_prepw<<<(tot2 + 255) / 256, 256>>>(conv2_w, w2, 1024, 64, tot2);
        k_prepcls<<<(512 * 512 + 255) / 256, 256>>>(cls_w, wclsT);
    }
    k_corr<<<dim3(NB, 4), 256>>>(f1, f2, out, invn1, invn2, xin);

    k_conv<<<dim3(8, NB), 512, SMEMC>>>(xin, w1, conv1_b, y1, 1024, 64);
    k_conv<<<dim3(4, NB), 512, SMEMC>>>(y1,  w2, conv2_b, y2,  512, 64);

    k_final<<<NB, 256>>>(y2, wclsT, out);
}

// round 9
// speedup vs baseline: 1.4939x; 1.1617x over previous
#include <cuda_runtime.h>
#include <cuda_bf16.h>
#include <cstdint>

#define NB 256
#define HW 256
#define CH 256
#define OFF_C1 512
#define OFF_C2 (512 + 16777216)

// padded-row geometry: every 16-ic row is 48B (32B data + 16B pad) -> conflict-free ldmatrix
#define XROW    24                    // bf16 elements per row (48B)
#define XCHUNK  6144                  // 256 px * 24 el  (12288B)
#define WCHUNK  27648                 // 9*128*24 el     (55296B)
// conv smem map
#define XS0 0
#define XS1 12336                     // 12288 + 48 zero row
#define WS0 24672
#define WS1 79968
#define MBOFF 135264
#define SMEMC 135296

// ---------------- device scratch ----------------
__device__ __nv_bfloat16 g_XIN[(size_t)NB * 64 * XCHUNK];   // [img][64cc][256px][24]
__device__ __nv_bfloat16 g_Y1 [(size_t)NB * 64 * XCHUNK];
__device__ __nv_bfloat16 g_Y2 [(size_t)NB * 32 * XCHUNK];
__device__ float         g_invn1[NB * HW];
__device__ float         g_invn2[NB * HW];
__device__ __nv_bfloat16 g_W1[(size_t)8 * 64 * WCHUNK];     // [ocb][cc][9][128][24]
__device__ __nv_bfloat16 g_W2[(size_t)4 * 64 * WCHUNK];
__device__ float         g_wclsT[512 * 512];

// ---------------- PTX helpers ----------------
__device__ __forceinline__ uint32_t smem_u32(const void* p) {
    uint32_t a;
    asm("{ .reg .u64 t; cvta.to.shared.u64 t, %1; cvt.u32.u64 %0, t; }" : "=r"(a) : "l"(p));
    return a;
}
#define MBAR_INIT(a, c)  asm volatile("mbarrier.init.shared.b64 [%0], %1;" :: "r"(a), "r"((uint32_t)(c)) : "memory")
#define MBAR_EXPECT_TX(a, n) \
    asm volatile("mbarrier.arrive.expect_tx.shared.b64 _, [%0], %1;" :: "r"(a), "r"((uint32_t)(n)) : "memory")
#define MBAR_WAIT(a, par) do {                                                    \
    uint32_t _m = (a), _p = (par), _d;                                            \
    asm volatile("{\n\t.reg .pred p;\n\t"                                         \
        "mbarrier.try_wait.parity.acquire.cta.shared::cta.b64 p, [%1], %2;\n\t"   \
        "selp.b32 %0,1,0,p;\n\t}" : "=r"(_d) : "r"(_m), "r"(_p) : "memory");      \
    if (!_d) {                                                                    \
        asm volatile("{\n\t.reg .pred P1;\n\tWL_%=:\n\t"                          \
            "mbarrier.try_wait.parity.acquire.cta.shared::cta.b64 P1, [%0], %1, 0x989680;\n\t" \
            "@P1 bra.uni WD_%=;\n\tbra.uni WL_%=;\n\tWD_%=:\n\t}"                 \
            :: "r"(_m), "r"(_p) : "memory");                                      \
    }                                                                             \
} while (0)
#define BULK_G2S(dst, src, bytes, bar) \
    asm volatile("cp.async.bulk.shared::cta.global.mbarrier::complete_tx::bytes [%0], [%1], %2, [%3];" \
        :: "r"(dst), "l"(src), "r"((uint32_t)(bytes)), "r"(bar) : "memory")
#define LDSM4(r0, r1, r2, r3, a) \
    asm volatile("ldmatrix.sync.aligned.m8n8.x4.shared.b16 {%0,%1,%2,%3}, [%4];" \
        : "=r"(r0), "=r"(r1), "=r"(r2), "=r"(r3) : "r"(a))
__device__ __forceinline__ void mma16816(float* c, const uint32_t* a, uint32_t b0, uint32_t b1) {
    asm volatile(
        "mma.sync.aligned.m16n8k16.row.col.f32.bf16.bf16.f32 "
        "{%0,%1,%2,%3}, {%4,%5,%6,%7}, {%8,%9}, {%0,%1,%2,%3};\n"
        : "+f"(c[0]), "+f"(c[1]), "+f"(c[2]), "+f"(c[3])
        : "r"(a[0]), "r"(a[1]), "r"(a[2]), "r"(a[3]), "r"(b0), "r"(b1));
}

// ---------------- K0: relu + channel norms + padded chunk layout ----------------
__global__ void k_norm(const float* __restrict__ f1, const float* __restrict__ f2,
                       __nv_bfloat16* __restrict__ xin,
                       float* __restrict__ invn1, float* __restrict__ invn2) {
    int b = blockIdx.x, p = threadIdx.x;
    const float* f1b = f1 + (size_t)b * 65536;
    const float* f2b = f2 + (size_t)b * 65536;
    __nv_bfloat16* xb = xin + (size_t)b * 64 * XCHUNK;
    float s1 = 0.f, s2 = 0.f;
    for (int ch = 0; ch < 16; ++ch) {
        __nv_bfloat16 h1[16], h2[16];
        #pragma unroll
        for (int i = 0; i < 16; ++i) {
            float v1 = fmaxf(f1b[(ch * 16 + i) * HW + p], 0.f);
            float v2 = fmaxf(f2b[(ch * 16 + i) * HW + p], 0.f);
            s1 += v1 * v1;  s2 += v2 * v2;
            h1[i] = __float2bfloat16(v1);
            h2[i] = __float2bfloat16(v2);
        }
        *(uint4*)&xb[(size_t)ch * XCHUNK + p * XROW]            = *(uint4*)&h1[0];
        *(uint4*)&xb[(size_t)ch * XCHUNK + p * XROW + 8]        = *(uint4*)&h1[8];
        *(uint4*)&xb[(size_t)(32 + ch) * XCHUNK + p * XROW]     = *(uint4*)&h2[0];
        *(uint4*)&xb[(size_t)(32 + ch) * XCHUNK + p * XROW + 8] = *(uint4*)&h2[8];
    }
    invn1[b * HW + p] = 1.0f / fmaxf(sqrtf(s1), 1e-12f);
    invn2[b * HW + p] = 1.0f / fmaxf(sqrtf(s2), 1e-12f);
}

// ---------------- weight prep: [ocb][cc][tap][128 oc][24] (48B padded rows) ----------------
__global__ void k_prepw(const float* __restrict__ w, __nv_bfloat16* __restrict__ o,
                        int IC, int NCC, int total) {
    int idx = blockIdx.x * blockDim.x + threadIdx.x;
    if (idx >= total) return;
    int ii = idx & 15;
    int oo = (idx >> 4) & 127;
    int r  = idx >> 11;
    int tp = r % 9;  r /= 9;
    int cc = r % NCC; int ocb = r / NCC;
    int oc = ocb * 128 + oo;
    int ic = cc * 16 + ii;
    size_t dst = ((((size_t)(ocb * NCC + cc) * 9 + tp) * 128 + oo) * XROW) + ii;
    o[dst] = __float2bfloat16(w[((size_t)oc * IC + ic) * 9 + tp]);
}

__global__ void k_prepcls(const float* __restrict__ w, float* __restrict__ o) {
    int idx = blockIdx.x * blockDim.x + threadIdx.x;
    if (idx >= 512 * 512) return;
    int ic = idx >> 9, oc = idx & 511;
    o[idx] = w[oc * 512 + ic];
}

// ---------------- K1: correlation GEMM (fp32 outputs + padded bf16 copies) ----------------
__global__ void __launch_bounds__(256) k_corr(
        const float* __restrict__ f1, const float* __restrict__ f2,
        float* __restrict__ out,
        const float* __restrict__ invn1, const float* __restrict__ invn2,
        __nv_bfloat16* __restrict__ xin) {
    __shared__ float A_s[16][132];
    __shared__ float B_s[16][132];
    int b = blockIdx.x, q = blockIdx.y;
    int kb = (q >> 1) * 128, pb = (q & 1) * 128;
    int t = threadIdx.x, tx = t & 15, ty = t >> 4;
    const float* f1b = f1 + (size_t)b * 65536;
    const float* f2b = f2 + (size_t)b * 65536;
    float acc[8][8];
    #pragma unroll
    for (int i = 0; i < 8; ++i)
        #pragma unroll
        for (int j = 0; j < 8; ++j) acc[i][j] = 0.f;
    for (int cc = 0; cc < 16; ++cc) {
        #pragma unroll
        for (int u = 0; u < 8; ++u) {
            int e = t + 256 * u;
            int c = e >> 7, k = e & 127;
            A_s[c][k] = fmaxf(f2b[(cc * 16 + c) * HW + kb + k], 0.f);
            B_s[c][k] = fmaxf(f1b[(cc * 16 + c) * HW + pb + k], 0.f);
        }
        __syncthreads();
        #pragma unroll
        for (int c = 0; c < 16; ++c) {
            float4 a0 = *(const float4*)&A_s[c][ty * 8];
            float4 a1 = *(const float4*)&A_s[c][ty * 8 + 4];
            float4 b0 = *(const float4*)&B_s[c][tx * 8];
            float4 b1 = *(const float4*)&B_s[c][tx * 8 + 4];
            float av[8] = {a0.x, a0.y, a0.z, a0.w, a1.x, a1.y, a1.z, a1.w};
            float bv[8] = {b0.x, b0.y, b0.z, b0.w, b1.x, b1.y, b1.z, b1.w};
            #pragma unroll
            for (int i = 0; i < 8; ++i)
                #pragma unroll
                for (int j = 0; j < 8; ++j) acc[i][j] += av[i] * bv[j];
        }
        __syncthreads();
    }
    float ik[8], ip[8];
    #pragma unroll
    for (int i = 0; i < 8; ++i) ik[i] = invn2[b * HW + kb + ty * 8 + i];
    #pragma unroll
    for (int j = 0; j < 8; ++j) ip[j] = invn1[b * HW + pb + tx * 8 + j];

    float vm[8][8];
    #pragma unroll
    for (int i = 0; i < 8; ++i)
        #pragma unroll
        for (int j = 0; j < 8; ++j) vm[i][j] = acc[i][j] * ik[i] * ip[j];

    float* c1 = out + OFF_C1 + (size_t)b * 65536;
    float* c2 = out + OFF_C2 + (size_t)b * 65536;
    #pragma unroll
    for (int i = 0; i < 8; ++i) {
        int k = kb + ty * 8 + i;
        #pragma unroll
        for (int j = 0; j < 8; ++j) {
            int p = pb + tx * 8 + j;
            c1[k * HW + p] = vm[i][j];
            c2[p * HW + k] = vm[i][j];
        }
    }
    // bf16 copies into padded chunk layout: corr1 -> chunks 16..31, corr2 -> 48..63
    __nv_bfloat16* xb = xin + (size_t)b * 64 * XCHUNK;
    int ch1 = 16 + (kb >> 4) + (ty >> 1);
    int sl1 = (ty & 1) * 8;
    #pragma unroll
    for (int j = 0; j < 8; ++j) {
        int p = pb + tx * 8 + j;
        __nv_bfloat16 h[8];
        #pragma unroll
        for (int i = 0; i < 8; ++i) h[i] = __float2bfloat16(vm[i][j]);
        *(uint4*)&xb[(size_t)ch1 * XCHUNK + p * XROW + sl1] = *(uint4*)&h[0];
    }
    int ch2 = 48 + (pb >> 4) + (tx >> 1);
    int sl2 = (tx & 1) * 8;
    #pragma unroll
    for (int i = 0; i < 8; ++i) {
        int k = kb + ty * 8 + i;
        __nv_bfloat16 h[8];
        #pragma unroll
        for (int j = 0; j < 8; ++j) h[j] = __float2bfloat16(vm[i][j]);
        *(uint4*)&xb[(size_t)ch2 * XCHUNK + k * XROW + sl2] = *(uint4*)&h[0];
    }
}

// ---------------- conv 3x3 implicit GEMM: ldmatrix + cp.async.bulk double-buffer ----------------
// grid (OC/128, NB), 512 threads = 16 warps (4M x 4N). Block tile M=128 oc, N=256 px.
__global__ void __launch_bounds__(512, 1) k_conv(
        const __nv_bfloat16* __restrict__ Xin,  // [img][NCC][256][24]
        const __nv_bfloat16* __restrict__ Wg,   // [ocb][NCC][9][128][24]
        const float* __restrict__ bias,
        __nv_bfloat16* __restrict__ Y,          // [img][OC/16][256][24]
        int OC, int NCC) {
    extern __shared__ __align__(16) char sraw[];
    uint32_t sb = smem_u32(sraw);
    int img = blockIdx.y, ocb = blockIdx.x;
    int t = threadIdx.x, lane = t & 31, wid = t >> 5;
    int g = lane >> 2, tg = lane & 3;
    int wm = (wid & 3) * 32, wn = (wid >> 2) * 64;

    const char* xg = (const char*)(Xin + (size_t)img * NCC * XCHUNK);
    const char* wg = (const char*)(Wg + (size_t)ocb * NCC * WCHUNK);

    uint32_t FB0 = sb + MBOFF, FB1 = sb + MBOFF + 8;
    if (t == 0) { MBAR_INIT(FB0, 1); MBAR_INIT(FB1, 1); }
    // zero halo rows (offset 12288 of both X buffers)
    if (t < 24) {
        int bi = t / 12, w = t % 12;
        *(uint32_t*)(sraw + (bi ? XS1 : XS0) + 12288 + w * 4) = 0u;
    }
    __syncthreads();
    if (t == 0) {
        #pragma unroll
        for (int s = 0; s < 2; ++s) {
            uint32_t fb = s ? FB1 : FB0;
            MBAR_EXPECT_TX(fb, 12288 + 55296);
            BULK_G2S(sb + (s ? XS1 : XS0), xg + (size_t)s * 12288, 12288, fb);
            BULK_G2S(sb + (s ? WS1 : WS0), wg + (size_t)s * 55296, 55296, fb);
        }
    }

    // per-lane ldmatrix address prep
    int r8 = lane & 7;
    uint32_t q1 = (lane >> 3) & 1;        // k-half (col +16B)
    int      q2 = (lane >> 4) & 1;        // j vs j+1
    uint32_t arel = (uint32_t)(wm + r8 + ((lane & 8) ? 8 : 0)) * 48 + ((lane & 16) ? 16 : 0);
    uint32_t xrel[4], mv[4];
    #pragma unroll
    for (int jj = 0; jj < 4; ++jj) {
        int px = wn + (2 * jj + q2) * 8 + r8;
        xrel[jj] = (uint32_t)px * 48 + q1 * 16;
        int xx = px & 15, yy = px >> 4;
        uint32_t m = 0;
        #pragma unroll
        for (int tp = 0; tp < 9; ++tp) {
            int dy = tp / 3 - 1, dx = tp % 3 - 1;
            if ((unsigned)(xx + dx) < 16u && (unsigned)(yy + dy) < 16u) m |= 1u << tp;
        }
        mv[jj] = m;
    }

    float acc[2][8][4];
    #pragma unroll
    for (int mi = 0; mi < 2; ++mi)
        #pragma unroll
        for (int j = 0; j < 8; ++j)
            #pragma unroll
            for (int r = 0; r < 4; ++r) acc[mi][j][r] = 0.f;

    for (int cc = 0; cc < NCC; ++cc) {
        int p = cc & 1, ph = (cc >> 1) & 1;
        MBAR_WAIT(p ? FB1 : FB0, ph);

        uint32_t Xa = sb + (p ? XS1 : XS0);
        uint32_t Wa = sb + (p ? WS1 : WS0);
        uint32_t za = Xa + 12288 + q1 * 16;
        uint32_t bb0 = Xa + xrel[0], bb1 = Xa + xrel[1];
        uint32_t bb2 = Xa + xrel[2], bb3 = Xa + xrel[3];
        uint32_t aA = Wa + arel;

        #pragma unroll
        for (int tp = 0; tp < 9; ++tp) {
            const int dy = tp / 3 - 1, dx = tp % 3 - 1;
            const int off = (dy * 16 + dx) * 48;
            uint32_t a0[4], a1[4];
            LDSM4(a0[0], a0[1], a0[2], a0[3], aA + tp * 6144);
            LDSM4(a1[0], a1[1], a1[2], a1[3], aA + tp * 6144 + 768);
            uint32_t bbv[4] = {bb0, bb1, bb2, bb3};
            #pragma unroll
            for (int jj = 0; jj < 4; ++jj) {
                uint32_t ba = ((mv[jj] >> tp) & 1u) ? (uint32_t)(bbv[jj] + off) : za;
                uint32_t b0, b1, b2, b3;
                LDSM4(b0, b1, b2, b3, ba);
                mma16816(acc[0][2 * jj],     a0, b0, b1);
                mma16816(acc[1][2 * jj],     a1, b0, b1);
                mma16816(acc[0][2 * jj + 1], a0, b2, b3);
                mma16816(acc[1][2 * jj + 1], a1, b2, b3);
            }
        }

        __syncthreads();                     // all warps done with buffer p
        if (t == 0 && cc + 2 < NCC) {
            int nn = cc + 2;
            uint32_t fb = p ? FB1 : FB0;
            MBAR_EXPECT_TX(fb, 12288 + 55296);
            BULK_G2S(Xa, xg + (size_t)nn * 12288, 12288, fb);
            BULK_G2S(Wa, wg + (size_t)nn * 55296, 55296, fb);
        }
    }

    // epilogue: bias + relu, transpose through smem, coalesced 16B stores
    __syncthreads();
    __nv_bfloat16* Sh = (__nv_bfloat16*)sraw;   // [256 px][136]
    #pragma unroll
    for (int mi = 0; mi < 2; ++mi) {
        int ocl = wm + mi * 16 + g;
        float bz0 = bias[ocb * 128 + ocl];
        float bz1 = bias[ocb * 128 + ocl + 8];
        #pragma unroll
        for (int j = 0; j < 8; ++j) {
            int px = wn + j * 8 + 2 * tg;
            const float* ac = acc[mi][j];
            Sh[px * 136 + ocl]           = __float2bfloat16(fmaxf(ac[0] + bz0, 0.f));
            Sh[(px + 1) * 136 + ocl]     = __float2bfloat16(fmaxf(ac[1] + bz0, 0.f));
            Sh[px * 136 + ocl + 8]       = __float2bfloat16(fmaxf(ac[2] + bz1, 0.f));
            Sh[(px + 1) * 136 + ocl + 8] = __float2bfloat16(fmaxf(ac[3] + bz1, 0.f));
        }
    }
    __syncthreads();
    __nv_bfloat16* Yb = Y + ((size_t)img * (OC >> 4) + ocb * 8) * XCHUNK;
    #pragma unroll
    for (int k2 = 0; k2 < 8; ++k2) {
        int idx = t + 512 * k2;               // 4096 = 8 chunks * 256 px * 2 halves
        int c8 = idx >> 9, rem = idx & 511, px = rem >> 1, hf = rem & 1;
        uint4 v = *(uint4*)&Sh[px * 136 + c8 * 16 + hf * 8];
        *(uint4*)&Yb[((size_t)c8 * 256 + px) * XROW + hf * 8] = v;
    }
}

// ---------------- final head: 1x1 (diag) + avgpool + softmax ----------------
__global__ void k_final(const __nv_bfloat16* __restrict__ Y2,
                        const float* __restrict__ wT,
                        float* __restrict__ out) {
    int b = blockIdx.x, p = threadIdx.x;
    const __nv_bfloat16* yb = Y2 + (size_t)b * 32 * XCHUNK;
    float a0 = 0.f, a1 = 0.f;
    for (int c = 0; c < 32; ++c) {
        __nv_bfloat16 h[16];
        *(uint4*)&h[0] = *(const uint4*)&yb[((size_t)c * 256 + p) * XROW];
        *(uint4*)&h[8] = *(const uint4*)&yb[((size_t)c * 256 + p) * XROW + 8];
        const float* wr = wT + (size_t)c * 16 * 512 + p;
        #pragma unroll
        for (int i = 0; i < 16; ++i) {
            float y = __bfloat162float(h[i]);
            a0 += wr[i * 512] * y;
            a1 += wr[i * 512 + 256] * y;
        }
    }
    a0 = fmaxf(a0, 0.f);
    a1 = fmaxf(a1, 0.f);
    __shared__ float s0[256], s1[256];
    s0[p] = a0; s1[p] = a1;
    __syncthreads();
    for (int st = 128; st > 0; st >>= 1) {
        if (p < st) { s0[p] += s0[p + st]; s1[p] += s1[p + st]; }
        __syncthreads();
    }
    if (p == 0) {
        float m0 = s0[0] * (1.0f / 256.0f);
        float m1 = s1[0] * (1.0f / 256.0f);
        float mx = fmaxf(m0, m1);
        float e0 = expf(m0 - mx), e1 = expf(m1 - mx);
        float inv = 1.0f / (e0 + e1);
        out[b * 2 + 0] = e0 * inv;
        out[b * 2 + 1] = e1 * inv;
    }
}

// ---------------- launch ----------------
extern "C" void kernel_launch(void* const* d_in, const int* in_sizes, int n_in,
                              void* d_out, int out_size) {
    const float* f1      = (const float*)d_in[0];
    const float* f2      = (const float*)d_in[1];
    const float* conv1_w = (const float*)d_in[2];
    const float* conv1_b = (const float*)d_in[3];
    const float* conv2_w = (const float*)d_in[4];
    const float* conv2_b = (const float*)d_in[5];
    const float* cls_w   = (const float*)d_in[6];
    float* out = (float*)d_out;

    __nv_bfloat16 *xin, *y1, *y2, *w1, *w2;
    float *invn1, *invn2, *wclsT;
    cudaGetSymbolAddress((void**)&xin,   g_XIN);
    cudaGetSymbolAddress((void**)&y1,    g_Y1);
    cudaGetSymbolAddress((void**)&y2,    g_Y2);
    cudaGetSymbolAddress((void**)&w1,    g_W1);
    cudaGetSymbolAddress((void**)&w2,    g_W2);
    cudaGetSymbolAddress((void**)&invn1, g_invn1);
    cudaGetSymbolAddress((void**)&invn2, g_invn2);
    cudaGetSymbolAddress((void**)&wclsT, g_wclsT);

    cudaFuncSetAttribute(k_conv, cudaFuncAttributeMaxDynamicSharedMemorySize, SMEMC);

    k_norm<<<NB, 256>>>(f1, f2, xin, invn1, invn2);
    {
        int tot1 = 8 * 64 * 9 * 2048;   // logical elements (pre-pad)
        k_prepw<<<(tot1 + 255) / 256, 256>>>(conv1_w, w1, 1024, 64, tot1);
        int tot2 = 4 * 64 * 9 * 2048;
        k_prepw<<<(tot2 + 255) / 256, 256>>>(conv2_w, w2, 1024, 64, tot2);
        k_prepcls<<<(512 * 512 + 255) / 256, 256>>>(cls_w, wclsT);
    }
    k_corr<<<dim3(NB, 4), 256>>>(f1, f2, out, invn1, invn2, xin);

    k_conv<<<dim3(8, NB), 512, SMEMC>>>(xin, w1, conv1_b, y1, 1024, 64);
    k_conv<<<dim3(4, NB), 512, SMEMC>>>(y1,  w2, conv2_b, y2,  512, 64);

    k_final<<<NB, 256>>>(y2, wclsT, out);
}